// round 17
// baseline (speedup 1.0000x reference)
#include <cuda_runtime.h>
#include <cuda_fp16.h>
#include <math.h>
#include <stdint.h>

#define EMBED 1024
#define HEADS 16
#define HEAD_DIM 64
#define HIDDEN 4096
#define BATCH 2
#define SEQ 2048
#define ROWS (BATCH * SEQ)
#define QKV_C (3 * EMBED)

// ---- GEMM tiling (fp16 operands) ----
#define BM 128
#define BN 128
#define BKH 64        // K halves per chunk
#define STAGES 3
#define APH 72        // A pitch (halves): 144B rows, conflict-free quads
#define BPH 136       // B pitch (halves): 272B rows, conflict-free quads
#define ASTGH (BM * APH)          // 9216 halves
#define BSTGH (BKH * BPH)         // 8704 halves
#define STGH (ASTGH + BSTGH)      // 17920 halves / stage
#define GEMM_SMEM (STGH * STAGES * 2)  // 107520 B

// ---- Attention tiling (fp16) ----
#define QROWS 128
#define QPH 72        // pitch for Q/K/V/P (halves)
#define KVSTGH (128 * QPH)        // K tile + V tile halves per stage
#define KVSTAGES 3
#define ATTN_SMEM ((QROWS * QPH + KVSTAGES * KVSTGH) * 2)  // 73728 B

// Scratch (no cudaMalloc allowed)
__device__ __half g_xn[(size_t)ROWS * EMBED];
__device__ __half g_qkv[(size_t)ROWS * QKV_C];
__device__ __half g_att[(size_t)ROWS * EMBED];
__device__ float  g_x1[(size_t)ROWS * EMBED];
__device__ __half g_h[(size_t)ROWS * HIDDEN];
__device__ __half g_wqkv[(size_t)EMBED * QKV_C];
__device__ __half g_wproj[(size_t)EMBED * EMBED];
__device__ __half g_wfc1[(size_t)EMBED * HIDDEN];
__device__ __half g_wfc2[(size_t)HIDDEN * EMBED];

// ---------------------------------------------------------------------------
__device__ __forceinline__ float gelu_exact(float x) {
    return 0.5f * x * (1.0f + erff(x * 0.70710678118654752f));
}

__device__ __forceinline__ void mma_fp16(float c[4], const uint32_t a[4],
                                         const uint32_t b[2]) {
    asm volatile(
        "mma.sync.aligned.m16n8k16.row.col.f32.f16.f16.f32 "
        "{%0,%1,%2,%3},{%4,%5,%6,%7},{%8,%9},{%0,%1,%2,%3};\n"
        : "+f"(c[0]), "+f"(c[1]), "+f"(c[2]), "+f"(c[3])
        : "r"(a[0]), "r"(a[1]), "r"(a[2]), "r"(a[3]), "r"(b[0]), "r"(b[1]));
}

__device__ __forceinline__ void cp16(uint32_t saddr, const void* gptr) {
    asm volatile("cp.async.cg.shared.global [%0], [%1], 16;\n" ::"r"(saddr),
                 "l"(gptr));
}

__device__ __forceinline__ void ldsm4(uint32_t r[4], uint32_t saddr) {
    asm volatile(
        "ldmatrix.sync.aligned.m8n8.x4.shared.b16 {%0,%1,%2,%3}, [%4];\n"
        : "=r"(r[0]), "=r"(r[1]), "=r"(r[2]), "=r"(r[3])
        : "r"(saddr));
}

__device__ __forceinline__ void ldsm4t(uint32_t r[4], uint32_t saddr) {
    asm volatile(
        "ldmatrix.sync.aligned.m8n8.x4.trans.shared.b16 {%0,%1,%2,%3}, [%4];\n"
        : "=r"(r[0]), "=r"(r[1]), "=r"(r[2]), "=r"(r[3])
        : "r"(saddr));
}

// ---------------------------------------------------------------------------
// Fused weight fp32 -> fp16 conversion for all four weight matrices.
// ---------------------------------------------------------------------------
#define WQ4 (EMBED * QKV_C / 4)
#define WP4 (EMBED * EMBED / 4)
#define W14 (EMBED * HIDDEN / 4)
#define W24 (HIDDEN * EMBED / 4)
#define WTOT4 (WQ4 + WP4 + W14 + W24)

__global__ __launch_bounds__(256) void cvt_all_kernel(
    const float* __restrict__ qw, const float* __restrict__ pw,
    const float* __restrict__ f1, const float* __restrict__ f2,
    __half* __restrict__ oq, __half* __restrict__ op,
    __half* __restrict__ o1, __half* __restrict__ o2) {
    int i = blockIdx.x * blockDim.x + threadIdx.x;
    if (i >= WTOT4) return;
    const float* src;
    __half* dst;
    int idx = i;
    if (idx < WQ4) {
        src = qw; dst = oq;
    } else if ((idx -= WQ4) < WP4) {
        src = pw; dst = op;
    } else if ((idx -= WP4) < W14) {
        src = f1; dst = o1;
    } else {
        idx -= W14;
        src = f2; dst = o2;
    }
    float4 v = ((const float4*)src)[idx];
    __half2 h0 = __floats2half2_rn(v.x, v.y);
    __half2 h1 = __floats2half2_rn(v.z, v.w);
    uint2 u;
    u.x = *(uint32_t*)&h0;
    u.y = *(uint32_t*)&h1;
    *(uint2*)(dst + 4 * (size_t)idx) = u;
}

// ---------------------------------------------------------------------------
// LayerNorm, warp-per-row (8 rows/CTA): pure shuffle reduction, no smem.
// Emits fp16 (consumed only as GEMM A operand).
// ---------------------------------------------------------------------------
__global__ __launch_bounds__(256) void ln_kernel(const float* __restrict__ x,
                                                 const float* __restrict__ w,
                                                 const float* __restrict__ b,
                                                 __half* __restrict__ out) {
    const int warp = threadIdx.x >> 5, lane = threadIdx.x & 31;
    const int row = blockIdx.x * 8 + warp;
    const float* xr = x + (size_t)row * EMBED;

    float4 v[4][2];
    float s = 0.f, q = 0.f;
#pragma unroll
    for (int c = 0; c < 4; c++) {
        const int col = c * 256 + lane * 8;
        v[c][0] = *(const float4*)(xr + col);
        v[c][1] = *(const float4*)(xr + col + 4);
#pragma unroll
        for (int p = 0; p < 2; p++) {
            s += v[c][p].x + v[c][p].y + v[c][p].z + v[c][p].w;
            q += v[c][p].x * v[c][p].x + v[c][p].y * v[c][p].y +
                 v[c][p].z * v[c][p].z + v[c][p].w * v[c][p].w;
        }
    }
#pragma unroll
    for (int o = 16; o > 0; o >>= 1) {
        s += __shfl_xor_sync(0xffffffffu, s, o);
        q += __shfl_xor_sync(0xffffffffu, q, o);
    }
    const float mu = s * (1.0f / EMBED);
    const float var = q * (1.0f / EMBED) - mu * mu;
    const float rstd = rsqrtf(var + 1e-5f);

    __half* orow = out + (size_t)row * EMBED;
#pragma unroll
    for (int c = 0; c < 4; c++) {
        const int col = c * 256 + lane * 8;
        float4 wv0 = *(const float4*)(w + col);
        float4 wv1 = *(const float4*)(w + col + 4);
        float4 bv0 = *(const float4*)(b + col);
        float4 bv1 = *(const float4*)(b + col + 4);
        __half2 h0 = __floats2half2_rn((v[c][0].x - mu) * rstd * wv0.x + bv0.x,
                                       (v[c][0].y - mu) * rstd * wv0.y + bv0.y);
        __half2 h1 = __floats2half2_rn((v[c][0].z - mu) * rstd * wv0.z + bv0.z,
                                       (v[c][0].w - mu) * rstd * wv0.w + bv0.w);
        __half2 h2 = __floats2half2_rn((v[c][1].x - mu) * rstd * wv1.x + bv1.x,
                                       (v[c][1].y - mu) * rstd * wv1.y + bv1.y);
        __half2 h3 = __floats2half2_rn((v[c][1].z - mu) * rstd * wv1.z + bv1.z,
                                       (v[c][1].w - mu) * rstd * wv1.w + bv1.w);
        uint4 u;
        u.x = *(uint32_t*)&h0;
        u.y = *(uint32_t*)&h1;
        u.z = *(uint32_t*)&h2;
        u.w = *(uint32_t*)&h3;
        *(uint4*)(orow + col) = u;
    }
}

// ---------------------------------------------------------------------------
// fp16 GEMM: 256 threads, 8 warps of 32x64, BKH=64, 3-stage cp.async,
// prefetch hoisted before compute. 2 CTAs/SM.
// EPI: 0 = bias -> half, 1 = bias + GELU -> half, 2 = bias + residual -> fp32
// ---------------------------------------------------------------------------
template <int EPI>
__global__ __launch_bounds__(256, 2) void gemm_fp16(
    const __half* __restrict__ A, const __half* __restrict__ W,
    const float* __restrict__ bias, const float* __restrict__ res,
    float* __restrict__ C, __half* __restrict__ Ch, int K, int Nc) {
    extern __shared__ __half smh[];
    const uint32_t sb = (uint32_t)__cvta_generic_to_shared(smh);
    const int tid = threadIdx.x;
    const int warp = tid >> 5, lane = tid & 31;
    const int g = lane >> 2, t = lane & 3;
    const int wm = (warp >> 1) * 32, wn = (warp & 1) * 64;
    const int brow = blockIdx.y, bcol = blockIdx.x;

    const __half* Aptr = A + (size_t)(brow * BM) * K;
    const __half* Wptr = W + (size_t)bcol * BN;

    const int ar0 = tid >> 3;          // 0..31, +32*i
    const int ac = tid & 7;
    const int br0 = tid >> 4;          // 0..15, +16*i
    const int bc = tid & 15;

    const uint32_t a_off =
        (uint32_t)(((lane & 7) + 8 * ((lane >> 3) & 1)) * APH * 2 +
                   (lane >> 4) * 16);
    const uint32_t b_off =
        (uint32_t)(((lane & 7) + 8 * ((lane >> 3) & 1)) * BPH * 2 +
                   (lane >> 4) * 16);

    float acc[2][8][4];
#pragma unroll
    for (int i = 0; i < 2; i++)
#pragma unroll
        for (int j = 0; j < 8; j++)
#pragma unroll
            for (int c = 0; c < 4; c++) acc[i][j][c] = 0.f;

    const int nch = K / BKH;

    auto issue = [&](int kt) {
        const int s = kt % STAGES;
        const uint32_t Asm = sb + (uint32_t)(s * STGH) * 2u;
        const uint32_t Bsm = Asm + ASTGH * 2u;
#pragma unroll
        for (int i = 0; i < 4; i++) {
            const int r = ar0 + 32 * i;
            cp16(Asm + (uint32_t)(r * APH + ac * 8) * 2u,
                 Aptr + (size_t)r * K + kt * BKH + ac * 8);
        }
#pragma unroll
        for (int i = 0; i < 4; i++) {
            const int r = br0 + 16 * i;
            cp16(Bsm + (uint32_t)(r * BPH + bc * 8) * 2u,
                 Wptr + (size_t)(kt * BKH + r) * Nc + bc * 8);
        }
    };

    issue(0);
    asm volatile("cp.async.commit_group;" ::: "memory");
    issue(1);
    asm volatile("cp.async.commit_group;" ::: "memory");

    for (int kt = 0; kt < nch; kt++) {
        asm volatile("cp.async.wait_group 1;" ::: "memory");
        __syncthreads();

        // Hoisted prefetch: stage (kt+2)%3 was last read at kt-1; the barrier
        // above orders those readers before these writes.
        if (kt + 2 < nch) issue(kt + 2);
        asm volatile("cp.async.commit_group;" ::: "memory");

        const int s = kt % STAGES;
        const uint32_t Astage = sb + (uint32_t)(s * STGH) * 2u;
        const uint32_t Bstage = Astage + ASTGH * 2u;

#pragma unroll
        for (int ks = 0; ks < 4; ks++) {
            uint32_t bfr[8][2];
#pragma unroll
            for (int jj = 0; jj < 4; jj++) {
                uint32_t r4[4];
                ldsm4t(r4, Bstage + (uint32_t)(ks * 16 * BPH * 2) +
                               (uint32_t)((wn + jj * 16) * 2) + b_off);
                bfr[2 * jj][0] = r4[0];
                bfr[2 * jj][1] = r4[1];
                bfr[2 * jj + 1][0] = r4[2];
                bfr[2 * jj + 1][1] = r4[3];
            }
#pragma unroll
            for (int i = 0; i < 2; i++) {
                uint32_t afr[4];
                ldsm4(afr, Astage + (uint32_t)((wm + i * 16) * APH * 2) +
                               (uint32_t)(ks * 32) + a_off);
#pragma unroll
                for (int j = 0; j < 8; j++) mma_fp16(acc[i][j], afr, bfr[j]);
            }
        }
    }

    // Epilogue
    const int colb = bcol * BN + wn;
#pragma unroll
    for (int i = 0; i < 2; i++) {
        const size_t r0 = (size_t)(brow * BM + wm + i * 16 + g);
        const size_t r1 = r0 + 8;
#pragma unroll
        for (int j = 0; j < 8; j++) {
            const int c0 = colb + j * 8 + 2 * t;
            float2 bv = *(const float2*)(bias + c0);
            float o0x = acc[i][j][0] + bv.x, o0y = acc[i][j][1] + bv.y;
            float o1x = acc[i][j][2] + bv.x, o1y = acc[i][j][3] + bv.y;
            if (EPI == 0) {
                *(__half2*)(Ch + r0 * Nc + c0) = __floats2half2_rn(o0x, o0y);
                *(__half2*)(Ch + r1 * Nc + c0) = __floats2half2_rn(o1x, o1y);
            } else if (EPI == 1) {
                *(__half2*)(Ch + r0 * Nc + c0) =
                    __floats2half2_rn(gelu_exact(o0x), gelu_exact(o0y));
                *(__half2*)(Ch + r1 * Nc + c0) =
                    __floats2half2_rn(gelu_exact(o1x), gelu_exact(o1y));
            } else {
                float2 r0v = *(const float2*)(res + r0 * Nc + c0);
                float2 r1v = *(const float2*)(res + r1 * Nc + c0);
                *(float2*)(C + r0 * Nc + c0) =
                    make_float2(o0x + r0v.x, o0y + r0v.y);
                *(float2*)(C + r1 * Nc + c0) =
                    make_float2(o1x + r1v.x, o1y + r1v.y);
            }
        }
    }
}

// ---------------------------------------------------------------------------
// fp16 flash attention: 8 warps, 128 q-rows/CTA, 64-key tiles, 3-stage
// cp.async K/V ring (single barrier per tile), ldmatrix fragments.
// ---------------------------------------------------------------------------
__global__ __launch_bounds__(256) void attn_mma(const __half* __restrict__ qkv,
                                                __half* __restrict__ out) {
    extern __shared__ __half sma[];
    __half* Qs = sma;  // [128][QPH]; warp's 16-row block doubles as P
    const uint32_t sb = (uint32_t)__cvta_generic_to_shared(sma);
    const uint32_t kvb = sb + (uint32_t)(QROWS * QPH * 2);

    const int bh = blockIdx.y;
    const int b = bh >> 4, h = bh & 15;
    const int qblk = blockIdx.x;
    const int tid = threadIdx.x;
    const int w = tid >> 5, lane = tid & 31;
    const int g = lane >> 2, t = lane & 3;
    const int wm = w * 16;

    const __half* qbase =
        qkv + (size_t)(b * SEQ + qblk * QROWS) * QKV_C + h * HEAD_DIM;
    const __half* kbase = qkv + (size_t)(b * SEQ) * QKV_C + EMBED + h * HEAD_DIM;
    const __half* vbase =
        qkv + (size_t)(b * SEQ) * QKV_C + 2 * EMBED + h * HEAD_DIM;

    auto issue_kv = [&](int tt, int s) {
        const uint32_t kd = kvb + (uint32_t)(s * KVSTGH) * 2u;
        const uint32_t vd = kd + (uint32_t)(64 * QPH * 2);
        const __half* kp = kbase + (size_t)(tt * 64) * QKV_C;
        const __half* vp = vbase + (size_t)(tt * 64) * QKV_C;
#pragma unroll
        for (int i = 0; i < 2; i++) {
            const int idx = tid + 256 * i;
            const int r = idx >> 3, c = idx & 7;
            cp16(kd + (uint32_t)(r * QPH + c * 8) * 2u,
                 kp + (size_t)r * QKV_C + c * 8);
            cp16(vd + (uint32_t)(r * QPH + c * 8) * 2u,
                 vp + (size_t)r * QKV_C + c * 8);
        }
    };

    issue_kv(0, 0);
    asm volatile("cp.async.commit_group;" ::: "memory");
    issue_kv(1, 1);
    asm volatile("cp.async.commit_group;" ::: "memory");

    // Stage Q (pre-scaled by 1/8, exact in fp16)
    {
        const __half2 sc = __floats2half2_rn(0.125f, 0.125f);
        for (int idx = tid; idx < QROWS * 32; idx += 256) {
            int r = idx >> 5, c2 = idx & 31;
            __half2 v = *(const __half2*)(qbase + (size_t)r * QKV_C + c2 * 2);
            *(__half2*)(Qs + r * QPH + c2 * 2) = __hmul2(v, sc);
        }
    }
    __syncthreads();

    const uint32_t a_off =
        (uint32_t)(((lane & 7) + 8 * ((lane >> 3) & 1)) * QPH * 2 +
                   (lane >> 4) * 16);
    const uint32_t k_off =
        (uint32_t)(((lane & 7) + 8 * (lane >> 4)) * QPH * 2 +
                   ((lane >> 3) & 1) * 16);
    const uint32_t v_off = a_off;
    const uint32_t pqbase = sb + (uint32_t)(wm * QPH * 2);

    uint32_t qa[4][4];
#pragma unroll
    for (int kk = 0; kk < 4; kk++) ldsm4(qa[kk], pqbase + kk * 32 + a_off);

    __half* Pw = Qs + wm * QPH;

    float m0 = -INFINITY, m1 = -INFINITY, l0 = 0.f, l1 = 0.f;
    float o[8][4];
#pragma unroll
    for (int j = 0; j < 8; j++)
#pragma unroll
        for (int c = 0; c < 4; c++) o[j][c] = 0.f;

    const int ntiles = SEQ / 64;
    for (int it = 0; it < ntiles; it++) {
        asm volatile("cp.async.wait_group 1;" ::: "memory");
        __syncthreads();

        // Refill ring stage (it+2)%3 — its readers finished before the barrier.
        if (it + 2 < ntiles) issue_kv(it + 2, (it + 2) % KVSTAGES);
        asm volatile("cp.async.commit_group;" ::: "memory");

        const int s = it % KVSTAGES;
        const uint32_t Kbase = kvb + (uint32_t)(s * KVSTGH) * 2u;
        const uint32_t Vbase = Kbase + (uint32_t)(64 * QPH * 2);

        // S = (Q/8) @ K^T
        float sacc[8][4];
#pragma unroll
        for (int j = 0; j < 8; j++)
#pragma unroll
            for (int c = 0; c < 4; c++) sacc[j][c] = 0.f;
#pragma unroll
        for (int kk = 0; kk < 4; kk++) {
            uint32_t kfr[8][2];
#pragma unroll
            for (int jj = 0; jj < 4; jj++) {
                uint32_t r4[4];
                ldsm4(r4, Kbase + (uint32_t)(jj * 16 * QPH * 2) + kk * 32 + k_off);
                kfr[2 * jj][0] = r4[0];
                kfr[2 * jj][1] = r4[1];
                kfr[2 * jj + 1][0] = r4[2];
                kfr[2 * jj + 1][1] = r4[3];
            }
#pragma unroll
            for (int j = 0; j < 8; j++) mma_fp16(sacc[j], qa[kk], kfr[j]);
        }

        // Online softmax (rows g, g+8; reduce over quad lanes)
        float mx0 = -INFINITY, mx1 = -INFINITY;
#pragma unroll
        for (int j = 0; j < 8; j++) {
            mx0 = fmaxf(mx0, fmaxf(sacc[j][0], sacc[j][1]));
            mx1 = fmaxf(mx1, fmaxf(sacc[j][2], sacc[j][3]));
        }
#pragma unroll
        for (int off = 1; off < 4; off <<= 1) {
            mx0 = fmaxf(mx0, __shfl_xor_sync(0xffffffffu, mx0, off));
            mx1 = fmaxf(mx1, __shfl_xor_sync(0xffffffffu, mx1, off));
        }
        float mn0 = fmaxf(m0, mx0), mn1 = fmaxf(m1, mx1);
        float a0 = __expf(m0 - mn0), a1 = __expf(m1 - mn1);
        float s0 = 0.f, s1 = 0.f;
#pragma unroll
        for (int j = 0; j < 8; j++) {
            float p0 = __expf(sacc[j][0] - mn0);
            float p1 = __expf(sacc[j][1] - mn0);
            float p2 = __expf(sacc[j][2] - mn1);
            float p3 = __expf(sacc[j][3] - mn1);
            s0 += p0 + p1;
            s1 += p2 + p3;
            *(__half2*)(Pw + g * QPH + j * 8 + 2 * t) = __floats2half2_rn(p0, p1);
            *(__half2*)(Pw + (g + 8) * QPH + j * 8 + 2 * t) =
                __floats2half2_rn(p2, p3);
        }
#pragma unroll
        for (int off = 1; off < 4; off <<= 1) {
            s0 += __shfl_xor_sync(0xffffffffu, s0, off);
            s1 += __shfl_xor_sync(0xffffffffu, s1, off);
        }
        l0 = l0 * a0 + s0;
        l1 = l1 * a1 + s1;
        m0 = mn0;
        m1 = mn1;
#pragma unroll
        for (int j = 0; j < 8; j++) {
            o[j][0] *= a0; o[j][1] *= a0; o[j][2] *= a1; o[j][3] *= a1;
        }
        __syncwarp();

        // O += P @ V
#pragma unroll
        for (int kk = 0; kk < 4; kk++) {
            uint32_t pa[4];
            ldsm4(pa, pqbase + kk * 32 + a_off);
            uint32_t vfr[8][2];
#pragma unroll
            for (int jj = 0; jj < 4; jj++) {
                uint32_t r4[4];
                ldsm4t(r4,
                       Vbase + (uint32_t)(kk * 16 * QPH * 2) + jj * 32 + v_off);
                vfr[2 * jj][0] = r4[0];
                vfr[2 * jj][1] = r4[1];
                vfr[2 * jj + 1][0] = r4[2];
                vfr[2 * jj + 1][1] = r4[3];
            }
#pragma unroll
            for (int j = 0; j < 8; j++) mma_fp16(o[j], pa, vfr[j]);
        }
    }

    // Epilogue: normalize -> fp16 (feeds proj GEMM A)
    float inv0 = 1.f / l0, inv1 = 1.f / l1;
    const int row0 = qblk * QROWS + wm + g;
    __half* ob = out + (size_t)(b * SEQ) * EMBED + h * HEAD_DIM;
#pragma unroll
    for (int j = 0; j < 8; j++) {
        *(__half2*)(ob + (size_t)row0 * EMBED + j * 8 + 2 * t) =
            __floats2half2_rn(o[j][0] * inv0, o[j][1] * inv0);
        *(__half2*)(ob + (size_t)(row0 + 8) * EMBED + j * 8 + 2 * t) =
            __floats2half2_rn(o[j][2] * inv1, o[j][3] * inv1);
    }
}

// ---------------------------------------------------------------------------
extern "C" void kernel_launch(void* const* d_in, const int* in_sizes, int n_in,
                              void* d_out, int out_size) {
    const float* x      = (const float*)d_in[0];
    const float* ln1_w  = (const float*)d_in[1];
    const float* ln1_b  = (const float*)d_in[2];
    const float* ln2_w  = (const float*)d_in[3];
    const float* ln2_b  = (const float*)d_in[4];
    const float* qkv_w  = (const float*)d_in[5];
    const float* qkv_b  = (const float*)d_in[6];
    const float* proj_w = (const float*)d_in[7];
    const float* proj_b = (const float*)d_in[8];
    const float* fc1_w  = (const float*)d_in[9];
    const float* fc1_b  = (const float*)d_in[10];
    const float* fc2_w  = (const float*)d_in[11];
    const float* fc2_b  = (const float*)d_in[12];
    float* out = (float*)d_out;

    void* p;
    cudaGetSymbolAddress(&p, g_xn);    __half* xn   = (__half*)p;
    cudaGetSymbolAddress(&p, g_qkv);   __half* qkv  = (__half*)p;
    cudaGetSymbolAddress(&p, g_att);   __half* att  = (__half*)p;
    cudaGetSymbolAddress(&p, g_x1);    float*  x1   = (float*)p;
    cudaGetSymbolAddress(&p, g_h);     __half* h    = (__half*)p;
    cudaGetSymbolAddress(&p, g_wqkv);  __half* wq   = (__half*)p;
    cudaGetSymbolAddress(&p, g_wproj); __half* wp   = (__half*)p;
    cudaGetSymbolAddress(&p, g_wfc1);  __half* w1   = (__half*)p;
    cudaGetSymbolAddress(&p, g_wfc2);  __half* w2   = (__half*)p;

    cudaFuncSetAttribute(attn_mma, cudaFuncAttributeMaxDynamicSharedMemorySize,
                         ATTN_SMEM);
    cudaFuncSetAttribute(gemm_fp16<0>, cudaFuncAttributeMaxDynamicSharedMemorySize,
                         GEMM_SMEM);
    cudaFuncSetAttribute(gemm_fp16<1>, cudaFuncAttributeMaxDynamicSharedMemorySize,
                         GEMM_SMEM);
    cudaFuncSetAttribute(gemm_fp16<2>, cudaFuncAttributeMaxDynamicSharedMemorySize,
                         GEMM_SMEM);

    // Weights -> fp16 (RN), one fused launch
    cvt_all_kernel<<<(WTOT4 + 255) / 256, 256>>>(qkv_w, proj_w, fc1_w, fc2_w,
                                                 wq, wp, w1, w2);

    // x1 = x + proj(attn(ln1(x)))
    ln_kernel<<<ROWS / 8, 256>>>(x, ln1_w, ln1_b, xn);
    gemm_fp16<0><<<dim3(QKV_C / BN, ROWS / BM), 256, GEMM_SMEM>>>(
        xn, wq, qkv_b, nullptr, nullptr, qkv, EMBED, QKV_C);
    attn_mma<<<dim3(SEQ / QROWS, BATCH * HEADS), 256, ATTN_SMEM>>>(qkv, att);
    gemm_fp16<2><<<dim3(EMBED / BN, ROWS / BM), 256, GEMM_SMEM>>>(
        att, wp, proj_b, x, x1, nullptr, EMBED, EMBED);

    // out = x1 + fc2(gelu(fc1(ln2(x1))))
    ln_kernel<<<ROWS / 8, 256>>>(x1, ln2_w, ln2_b, xn);
    gemm_fp16<1><<<dim3(HIDDEN / BN, ROWS / BM), 256, GEMM_SMEM>>>(
        xn, w1, fc1_b, nullptr, nullptr, h, EMBED, HIDDEN);
    gemm_fp16<2><<<dim3(EMBED / BN, ROWS / BM), 256, GEMM_SMEM>>>(
        h, w2, fc2_b, x1, out, nullptr, HIDDEN, EMBED);
}